// round 11
// baseline (speedup 1.0000x reference)
#include <cuda_runtime.h>
#include <cuda_bf16.h>

// LIFActivation, single fused kernel, barrier-free per-WARP threshold search.
//
// out(x) is a 4-threshold step function of x: n_spikes(x) is monotone for
// fixed scale and thresholds lie within a few ulp of RN(k*s/4). Every warp
// finds X1..X4 itself (lanes 8g..8g+7 handle target g+1) with a 2-round
// 9-ary ballot search over a +/-16-ulp window, probing the EXACT reference
// fp32 sequence. Bracket-verified with a full-range fallback loop ->
// correctness unconditional. No __syncthreads, no shared memory: warps are
// fully decoupled; the search hides under each warp's own in-flight loads.
// 4 independent v8 (256-bit) streams per thread, block 128 (regs ~56 ->
// ~9 blocks/SM).

__device__ __forceinline__ int nspikes_ref(float x, float s) {
    float c = __fdiv_rn(fmaxf(x, 0.0f), s);  // IEEE RN div, exact ref semantics
    float v = 0.0f;
    int n = 0;
#pragma unroll
    for (int t = 0; t < 4; ++t) {
        v += c;
        if (v >= 1.0f) {  // H(v-1)==1 <=> v>=1
            v -= 1.0f;
            n += 1;
        }
    }
    return n;
}

// Warp-collective: returns X (thresholds for n>=1..4) to ALL lanes.
// Invariant: n(lo) < target (or lo==0), n(hi) >= target; answer = hi.
__device__ __forceinline__ float4 warp_thresholds(float s) {
    const unsigned FULL = 0xFFFFFFFFu;
    const unsigned FMAX = 0x7F7FFFFFu;
    int lane = threadIdx.x & 31;
    int grp  = lane >> 3;
    int sub  = lane & 7;

    int target = grp + 1;
    float qs = 0.25f * s;                   // exact (power-of-2 scale)
    unsigned cb = __float_as_uint((float)target * qs);

    const unsigned W = 16u;
    unsigned lo = (cb > W) ? cb - W : 0u;
    unsigned hi = (cb >= FMAX - W) ? FMAX : cb + W;

    bool lo_sat = nspikes_ref(__uint_as_float(lo), s) >= target;
    bool hi_sat = nspikes_ref(__uint_as_float(hi), s) >= target;
    bool feasible = true;
    bool windowed = true;
    if (lo_sat) {                 // threshold below window: bracket (0, lo]
        hi = lo; lo = 0u; windowed = false;
    } else if (!hi_sat) {         // threshold above window
        if (nspikes_ref(__uint_as_float(FMAX), s) >= target) {
            lo = hi; hi = FMAX; windowed = false;
        } else {
            feasible = false;     // never reaches target spikes
            lo = hi;
        }
    }

    // One 9-ary narrowing round: range -> ceil(range/9)-ish (<=4 for range 32).
    auto round9 = [&](void) {
        unsigned long long range = (unsigned long long)(hi - lo);
        unsigned p = lo + (unsigned)(range * (unsigned long long)(sub + 1) / 9ull);
        bool sat = (range > 1ull) && (nspikes_ref(__uint_as_float(p), s) >= target);
        unsigned bal = __ballot_sync(FULL, sat);
        if (range > 1ull) {
            unsigned g = (bal >> (grp * 8)) & 0xFFu;
            if (g == 0u) {
                lo += (unsigned)(range * 8ull / 9ull);
            } else {
                int j = __ffs((int)g) - 1;
                hi = lo + (unsigned)(range * (unsigned long long)(j + 1) / 9ull);
                if (j > 0)
                    lo += (unsigned)(range * (unsigned long long)j / 9ull);
            }
        }
    };

    // Window case: exactly 2 rounds converge (32 -> <=4 -> <=1).
    round9();
    round9();

    if (__any_sync(FULL, (hi - lo) > 1u)) {
        // Fallback (bracket escaped the window): full binary-style loop.
        for (int it = 0; it < 12; ++it) {
            bool conv = (hi - lo) <= 1u;
            if (__all_sync(FULL, conv)) break;
            round9();
        }
        (void)windowed;
    }

    float Xg = feasible ? __uint_as_float(hi) : __int_as_float(0x7F800000);
    float4 X;
    X.x = __shfl_sync(FULL, Xg, 0);
    X.y = __shfl_sync(FULL, Xg, 8);
    X.z = __shfl_sync(FULL, Xg, 16);
    X.w = __shfl_sync(FULL, Xg, 24);
    return X;
}

// 256-bit global load/store (Blackwell sm_100+), default cache policy.
__device__ __forceinline__ void ldg_v8(const float* __restrict__ p, float* r) {
    asm("ld.global.nc.v8.f32 {%0,%1,%2,%3,%4,%5,%6,%7}, [%8];"
        : "=f"(r[0]), "=f"(r[1]), "=f"(r[2]), "=f"(r[3]),
          "=f"(r[4]), "=f"(r[5]), "=f"(r[6]), "=f"(r[7])
        : "l"(p));
}
__device__ __forceinline__ void stg_v8(float* __restrict__ p, const float* r) {
    asm volatile("st.global.v8.f32 [%0], {%1,%2,%3,%4,%5,%6,%7,%8};"
        :: "l"(p),
           "f"(r[0]), "f"(r[1]), "f"(r[2]), "f"(r[3]),
           "f"(r[4]), "f"(r[5]), "f"(r[6]), "f"(r[7])
        : "memory");
}

__device__ __forceinline__ float lif_sel(float x, float4 X, float4 V) {
    float r = 0.0f;
    r = (x >= X.x) ? V.x : r;
    r = (x >= X.y) ? V.y : r;
    r = (x >= X.z) ? V.z : r;
    r = (x >= X.w) ? V.w : r;
    return r;   // NaN -> all false -> 0, matches reference
}

// 4 independent 32-byte streams per thread, front-batched before the search.
__global__ void __launch_bounds__(128)
lif_fused_kernel(const float* __restrict__ x,
                 const float* __restrict__ scale_ptr,
                 float* __restrict__ out, int n8, int quarter) {
    int tid = threadIdx.x;
    int i   = blockIdx.x * blockDim.x + tid;

    int  idx[4];
    bool ok[4];
    float a[4][8];
#pragma unroll
    for (int k = 0; k < 4; ++k) {
        idx[k] = i + k * quarter;
        ok[k]  = idx[k] < n8;
    }
#pragma unroll
    for (int k = 0; k < 4; ++k)
        if (ok[k]) ldg_v8(x + (size_t)idx[k] * 8, a[k]);

    // Per-warp search, hidden under this warp's own load latency.
    float s = fmaxf(__ldg(scale_ptr), 1e-12f);
    float4 X = warp_thresholds(s);
    float qs = 0.25f * s;
    float4 V = make_float4(qs, 2.0f * qs, 3.0f * qs, 4.0f * qs);

#pragma unroll
    for (int k = 0; k < 4; ++k) {
        if (ok[k]) {
            float r[8];
#pragma unroll
            for (int e = 0; e < 8; ++e) r[e] = lif_sel(a[k][e], X, V);
            stg_v8(out + (size_t)idx[k] * 8, r);
        }
    }
}

extern "C" void kernel_launch(void* const* d_in, const int* in_sizes, int n_in,
                              void* d_out, int out_size) {
    const float* x     = (const float*)d_in[0];
    const float* scale = (const float*)d_in[1];
    float* out = (float*)d_out;

    int n  = out_size;       // 4096*8192 = 2^25 (divisible by 32)
    int n8 = n >> 3;         // v8 (32-byte) chunk count
    int quarter = (n8 + 3) >> 2;

    const int threads = 128;
    int blocks = (quarter + threads - 1) / threads;
    lif_fused_kernel<<<blocks, threads>>>(x, scale, out, n8, quarter);
}

// round 12
// speedup vs baseline: 1.0294x; 1.0294x over previous
#include <cuda_runtime.h>
#include <cuda_bf16.h>

// LIFActivation, single fused kernel, barrier-free per-WARP threshold search.
// R11 + L2::256B fetch-granularity hint on the read stream (aligned 256B
// sectors by construction; stores keep default policy per R8 finding).
//
// out(x) is a 4-threshold step function of x: n_spikes(x) is monotone for
// fixed scale and thresholds lie within a few ulp of RN(k*s/4). Every warp
// finds X1..X4 itself (lanes 8g..8g+7 handle target g+1) with a 2-round
// 9-ary ballot search over a +/-16-ulp window, probing the EXACT reference
// fp32 sequence. Bracket-verified with a full-range fallback loop ->
// correctness unconditional. No __syncthreads, no shared memory.
// 4 independent v8 (256-bit) streams per thread, block 128.

__device__ __forceinline__ int nspikes_ref(float x, float s) {
    float c = __fdiv_rn(fmaxf(x, 0.0f), s);  // IEEE RN div, exact ref semantics
    float v = 0.0f;
    int n = 0;
#pragma unroll
    for (int t = 0; t < 4; ++t) {
        v += c;
        if (v >= 1.0f) {  // H(v-1)==1 <=> v>=1
            v -= 1.0f;
            n += 1;
        }
    }
    return n;
}

// Warp-collective: returns X (thresholds for n>=1..4) to ALL lanes.
// Invariant: n(lo) < target (or lo==0), n(hi) >= target; answer = hi.
__device__ __forceinline__ float4 warp_thresholds(float s) {
    const unsigned FULL = 0xFFFFFFFFu;
    const unsigned FMAX = 0x7F7FFFFFu;
    int lane = threadIdx.x & 31;
    int grp  = lane >> 3;
    int sub  = lane & 7;

    int target = grp + 1;
    float qs = 0.25f * s;                   // exact (power-of-2 scale)
    unsigned cb = __float_as_uint((float)target * qs);

    const unsigned W = 16u;
    unsigned lo = (cb > W) ? cb - W : 0u;
    unsigned hi = (cb >= FMAX - W) ? FMAX : cb + W;

    bool lo_sat = nspikes_ref(__uint_as_float(lo), s) >= target;
    bool hi_sat = nspikes_ref(__uint_as_float(hi), s) >= target;
    bool feasible = true;
    if (lo_sat) {                 // threshold below window: bracket (0, lo]
        hi = lo; lo = 0u;
    } else if (!hi_sat) {         // threshold above window
        if (nspikes_ref(__uint_as_float(FMAX), s) >= target) {
            lo = hi; hi = FMAX;
        } else {
            feasible = false;     // never reaches target spikes
            lo = hi;
        }
    }

    // One 9-ary narrowing round: range 32 -> <=4 -> <=1.
    auto round9 = [&](void) {
        unsigned long long range = (unsigned long long)(hi - lo);
        unsigned p = lo + (unsigned)(range * (unsigned long long)(sub + 1) / 9ull);
        bool sat = (range > 1ull) && (nspikes_ref(__uint_as_float(p), s) >= target);
        unsigned bal = __ballot_sync(FULL, sat);
        if (range > 1ull) {
            unsigned g = (bal >> (grp * 8)) & 0xFFu;
            if (g == 0u) {
                lo += (unsigned)(range * 8ull / 9ull);
            } else {
                int j = __ffs((int)g) - 1;
                hi = lo + (unsigned)(range * (unsigned long long)(j + 1) / 9ull);
                if (j > 0)
                    lo += (unsigned)(range * (unsigned long long)j / 9ull);
            }
        }
    };

    round9();
    round9();

    if (__any_sync(FULL, (hi - lo) > 1u)) {
        // Fallback (bracket escaped the window): converges from any range.
        for (int it = 0; it < 12; ++it) {
            bool conv = (hi - lo) <= 1u;
            if (__all_sync(FULL, conv)) break;
            round9();
        }
    }

    float Xg = feasible ? __uint_as_float(hi) : __int_as_float(0x7F800000);
    float4 X;
    X.x = __shfl_sync(FULL, Xg, 0);
    X.y = __shfl_sync(FULL, Xg, 8);
    X.z = __shfl_sync(FULL, Xg, 16);
    X.w = __shfl_sync(FULL, Xg, 24);
    return X;
}

// 256-bit global load with 256B L2 fetch granularity; default-policy store.
__device__ __forceinline__ void ldg_v8(const float* __restrict__ p, float* r) {
    asm("ld.global.nc.L2::256B.v8.f32 {%0,%1,%2,%3,%4,%5,%6,%7}, [%8];"
        : "=f"(r[0]), "=f"(r[1]), "=f"(r[2]), "=f"(r[3]),
          "=f"(r[4]), "=f"(r[5]), "=f"(r[6]), "=f"(r[7])
        : "l"(p));
}
__device__ __forceinline__ void stg_v8(float* __restrict__ p, const float* r) {
    asm volatile("st.global.v8.f32 [%0], {%1,%2,%3,%4,%5,%6,%7,%8};"
        :: "l"(p),
           "f"(r[0]), "f"(r[1]), "f"(r[2]), "f"(r[3]),
           "f"(r[4]), "f"(r[5]), "f"(r[6]), "f"(r[7])
        : "memory");
}

__device__ __forceinline__ float lif_sel(float x, float4 X, float4 V) {
    float r = 0.0f;
    r = (x >= X.x) ? V.x : r;
    r = (x >= X.y) ? V.y : r;
    r = (x >= X.z) ? V.z : r;
    r = (x >= X.w) ? V.w : r;
    return r;   // NaN -> all false -> 0, matches reference
}

// 4 independent 32-byte streams per thread, front-batched before the search.
__global__ void __launch_bounds__(128)
lif_fused_kernel(const float* __restrict__ x,
                 const float* __restrict__ scale_ptr,
                 float* __restrict__ out, int n8, int quarter) {
    int tid = threadIdx.x;
    int i   = blockIdx.x * blockDim.x + tid;

    int  idx[4];
    bool ok[4];
    float a[4][8];
#pragma unroll
    for (int k = 0; k < 4; ++k) {
        idx[k] = i + k * quarter;
        ok[k]  = idx[k] < n8;
    }
#pragma unroll
    for (int k = 0; k < 4; ++k)
        if (ok[k]) ldg_v8(x + (size_t)idx[k] * 8, a[k]);

    // Per-warp search, hidden under this warp's own load latency.
    float s = fmaxf(__ldg(scale_ptr), 1e-12f);
    float4 X = warp_thresholds(s);
    float qs = 0.25f * s;
    float4 V = make_float4(qs, 2.0f * qs, 3.0f * qs, 4.0f * qs);

#pragma unroll
    for (int k = 0; k < 4; ++k) {
        if (ok[k]) {
            float r[8];
#pragma unroll
            for (int e = 0; e < 8; ++e) r[e] = lif_sel(a[k][e], X, V);
            stg_v8(out + (size_t)idx[k] * 8, r);
        }
    }
}

extern "C" void kernel_launch(void* const* d_in, const int* in_sizes, int n_in,
                              void* d_out, int out_size) {
    const float* x     = (const float*)d_in[0];
    const float* scale = (const float*)d_in[1];
    float* out = (float*)d_out;

    int n  = out_size;       // 4096*8192 = 2^25 (divisible by 32)
    int n8 = n >> 3;         // v8 (32-byte) chunk count
    int quarter = (n8 + 3) >> 2;

    const int threads = 128;
    int blocks = (quarter + threads - 1) / threads;
    lif_fused_kernel<<<blocks, threads>>>(x, scale, out, n8, quarter);
}